// round 3
// baseline (speedup 1.0000x reference)
#include <cuda_runtime.h>
#include <cstdint>

// lstm_model_8873402433789 R2 — fused LSTM, fp32x2-packed, gate-major x,
// 2 independent rows per warp (tail-latency hiding), LDS.128 splat reads.

#define ULL unsigned long long

static __device__ __forceinline__ ULL pk2(float lo, float hi) {
    ULL r;
    asm("mov.b64 %0, {%1, %2};" : "=l"(r) : "f"(lo), "f"(hi));
    return r;
}
static __device__ __forceinline__ void upk2(ULL v, float& lo, float& hi) {
    asm("mov.b64 {%0, %1}, %2;" : "=f"(lo), "=f"(hi) : "l"(v));
}
static __device__ __forceinline__ ULL fma2(ULL a, ULL b, ULL c) {
    ULL d;
    asm("fma.rn.f32x2 %0, %1, %2, %3;" : "=l"(d) : "l"(a), "l"(b), "l"(c));
    return d;
}
static __device__ __forceinline__ float sigf(float v) {
    return __fdividef(1.0f, 1.0f + __expf(-v));
}

#define BB 8192
#define TT 200
#define FF 16
#define HH 32
#define DD 60
// 25 chunks x 8 steps; 8*16 floats = 32 float4 per chunk per row.

__global__ void __launch_bounds__(128, 2) lstm_fused2_kernel(
    const float* __restrict__ x,   // [B, T, F]
    const float* __restrict__ W,   // [F, 4H]
    const float* __restrict__ U,   // [H, 4H]
    const float* __restrict__ b,   // [4H]
    const float* __restrict__ W1,  // [H, D]
    const float* __restrict__ b1,  // [D]
    const float* __restrict__ W2,  // [H, D]
    const float* __restrict__ b2,  // [D]
    float* __restrict__ out)       // [2, B, D]
{
    // [warp][row][buf][...] splat buffers, 16B-aligned for LDS.128
    __shared__ __align__(16) ULL hs[4][2][2][32];    // h splats (h,h)
    __shared__ __align__(16) ULL xs[4][2][2][128];   // x splats, [step*16+f]

    const int w  = threadIdx.x >> 5;
    const int j  = threadIdx.x & 31;
    const int row0 = blockIdx.x * 8 + w * 2;   // this warp's two rows

    // ---- Weights into registers (shared across both rows) ----
    ULL u01[32], u23[32];
#pragma unroll
    for (int k = 0; k < 32; ++k) {
        const float* Uk = U + k * 128;
        u01[k] = pk2(Uk[j],      Uk[32 + j]);
        u23[k] = pk2(Uk[64 + j], Uk[96 + j]);
    }
    // Gate-major W: w01[f] = (W[f][j], W[f][32+j]) so splat(x_f) FMAs straight
    // into the (i,f) / (c,o) gate accumulators.
    ULL w01[16], w23[16];
#pragma unroll
    for (int f = 0; f < 16; ++f) {
        const float* Wf = W + f * 128;
        w01[f] = pk2(Wf[j],      Wf[32 + j]);
        w23[f] = pk2(Wf[64 + j], Wf[96 + j]);
    }
    const ULL b01 = pk2(b[j],      b[32 + j]);
    const ULL b23 = pk2(b[64 + j], b[96 + j]);

    const float4* xA = (const float4*)(x + (size_t)row0 * (TT * FF));
    const float4* xB = (const float4*)(x + (size_t)(row0 + 1) * (TT * FF));

    // ---- Init h splats + stage chunk 0 as splats ----
    hs[w][0][0][j] = 0ULL;
    hs[w][1][0][j] = 0ULL;
    {
        float4 va = xA[j], vb = xB[j];
        int si = (j >> 2) * 16 + (j & 3) * 4;
        ULL* d0 = &xs[w][0][0][si];
        d0[0] = pk2(va.x, va.x); d0[1] = pk2(va.y, va.y);
        d0[2] = pk2(va.z, va.z); d0[3] = pk2(va.w, va.w);
        ULL* d1 = &xs[w][1][0][si];
        d1[0] = pk2(vb.x, vb.x); d1[1] = pk2(vb.y, vb.y);
        d1[2] = pk2(vb.z, vb.z); d1[3] = pk2(vb.w, vb.w);
    }
    __syncwarp();

    float c0 = 0.0f, c1 = 0.0f;

    for (int chunk = 0; chunk < 25; ++chunk) {
        const int cb = chunk & 1;
        // Prefetch next chunk straight into the spare buffer (clamped last).
        {
            int nxt = chunk + 1; if (nxt > 24) nxt = 24;
            float4 pa = xA[nxt * 32 + j];
            float4 pb = xB[nxt * 32 + j];
            int si = (j >> 2) * 16 + (j & 3) * 4;
            ULL* d0 = &xs[w][0][cb ^ 1][si];
            d0[0] = pk2(pa.x, pa.x); d0[1] = pk2(pa.y, pa.y);
            d0[2] = pk2(pa.z, pa.z); d0[3] = pk2(pa.w, pa.w);
            ULL* d1 = &xs[w][1][cb ^ 1][si];
            d1[0] = pk2(pb.x, pb.x); d1[1] = pk2(pb.y, pb.y);
            d1[2] = pk2(pb.z, pb.z); d1[3] = pk2(pb.w, pb.w);
        }

#pragma unroll 2
        for (int s = 0; s < 8; ++s) {
            const int par = s & 1;     // global t = chunk*8+s, chunk*8 even
            ULL a01 = b01, a23 = b23;  // row 0 gate accumulators (i,f)/(c,o)
            ULL g01 = b01, g23 = b23;  // row 1

            // x-part (h-independent; schedulable into prior step's tail)
            const ulonglong2* xq0 = (const ulonglong2*)&xs[w][0][cb][s * 16];
            const ulonglong2* xq1 = (const ulonglong2*)&xs[w][1][cb][s * 16];
#pragma unroll
            for (int p = 0; p < 8; ++p) {
                ulonglong2 v0 = xq0[p];
                a01 = fma2(v0.x, w01[2 * p],     a01);
                a23 = fma2(v0.x, w23[2 * p],     a23);
                a01 = fma2(v0.y, w01[2 * p + 1], a01);
                a23 = fma2(v0.y, w23[2 * p + 1], a23);
                ulonglong2 v1 = xq1[p];
                g01 = fma2(v1.x, w01[2 * p],     g01);
                g23 = fma2(v1.x, w23[2 * p],     g23);
                g01 = fma2(v1.y, w01[2 * p + 1], g01);
                g23 = fma2(v1.y, w23[2 * p + 1], g23);
            }

            // h-part (recurrent)
            const ulonglong2* hq0 = (const ulonglong2*)&hs[w][0][par][0];
            const ulonglong2* hq1 = (const ulonglong2*)&hs[w][1][par][0];
#pragma unroll
            for (int k = 0; k < 16; ++k) {
                ulonglong2 h0 = hq0[k];
                a01 = fma2(h0.x, u01[2 * k],     a01);
                a23 = fma2(h0.x, u23[2 * k],     a23);
                a01 = fma2(h0.y, u01[2 * k + 1], a01);
                a23 = fma2(h0.y, u23[2 * k + 1], a23);
                ulonglong2 h1 = hq1[k];
                g01 = fma2(h1.x, u01[2 * k],     g01);
                g23 = fma2(h1.x, u23[2 * k],     g23);
                g01 = fma2(h1.y, u01[2 * k + 1], g01);
                g23 = fma2(h1.y, u23[2 * k + 1], g23);
            }

            // Tails (rows independent -> interleave)
            {
                float gi, gf, gc, go;
                upk2(a01, gi, gf); upk2(a23, gc, go);
                float ii = sigf(gi), ff = sigf(gf), oo = sigf(go);
                c0 = ff * c0 + ii * fmaxf(gc, 0.0f);
                float h0 = oo * fmaxf(c0, 0.0f);
                hs[w][0][par ^ 1][j] = pk2(h0, h0);
            }
            {
                float gi, gf, gc, go;
                upk2(g01, gi, gf); upk2(g23, gc, go);
                float ii = sigf(gi), ff = sigf(gf), oo = sigf(go);
                c1 = ff * c1 + ii * fmaxf(gc, 0.0f);
                float h1 = oo * fmaxf(c1, 0.0f);
                hs[w][1][par ^ 1][j] = pk2(h1, h1);
            }
            __syncwarp();
        }
        __syncwarp();   // prefetch stores visible before next chunk reads
    }

    // ---- Output heads for both rows (final h in buffer 0: t=200 even) ----
    float* outL = out;
    float* outA = out + (size_t)BB * DD;
#pragma unroll
    for (int r = 0; r < 2; ++r) {
        const float* hf = (const float*)&hs[w][r][0][0];  // hf[2k] = h_k
        const size_t row = row0 + r;
#pragma unroll
        for (int rep = 0; rep < 2; ++rep) {
            int d = j + rep * 32;
            if (d < DD) {
                float aL = b1[d], aA = b2[d];
#pragma unroll
                for (int k = 0; k < 32; ++k) {
                    float hk = hf[2 * k];
                    aL = fmaf(hk, W1[k * DD + d], aL);
                    aA = fmaf(hk, W2[k * DD + d], aA);
                }
                outL[row * DD + d] = aL;
                outA[row * DD + d] = aA;
            }
        }
    }
}

extern "C" void kernel_launch(void* const* d_in, const int* in_sizes, int n_in,
                              void* d_out, int out_size) {
    const float* x  = (const float*)d_in[0];
    const float* W  = (const float*)d_in[1];
    const float* U  = (const float*)d_in[2];
    const float* b  = (const float*)d_in[3];
    const float* W1 = (const float*)d_in[4];
    const float* b1 = (const float*)d_in[5];
    const float* W2 = (const float*)d_in[6];
    const float* b2 = (const float*)d_in[7];
    float* out = (float*)d_out;

    // 8192 rows, 2 rows/warp, 4 warps/block -> 1024 blocks
    lstm_fused2_kernel<<<1024, 128>>>(x, W, U, b, W1, b1, W2, b2, out);
}

// round 5
// speedup vs baseline: 1.9185x; 1.9185x over previous
#include <cuda_runtime.h>
#include <cuda_bf16.h>
#include <cstdint>

// lstm_model_8873402433789 R5 — warp-level mma.sync (bf16, m16n8k16) LSTM.
// 128 CTAs x 64 rows. Gates = Wt[128 gates, 96 K] . act[96 K, 64 rows] per step,
// hi/lo bf16 compensation (9 k16 MMA products). Warp (mg,ng) owns units
// 16mg..+15 x rows 16ng..+15 via m-tiles at gate offsets {0,32,64,96}+16mg —
// so i/f/c/o of each unit land in ONE thread's D fragments (no gate exchange).

#define TT 200
#define ROWS 64
#define KS 104          // padded K stride (bf16 elems): 96 data + 8 pad
#define DD 60

static __device__ __forceinline__ uint32_t s2u(const void* p) {
    uint32_t a;
    asm("{ .reg .u64 t; cvta.to.shared.u64 t, %1; cvt.u32.u64 %0, t; }"
        : "=r"(a) : "l"(p));
    return a;
}
static __device__ __forceinline__ float bhi(float a) {
    return __bfloat162float(__float2bfloat16_rn(a));
}
static __device__ __forceinline__ uint32_t bpack(float a, float b) {
    __nv_bfloat162 t = __float22bfloat162_rn(make_float2(a, b));
    return *(uint32_t*)&t;
}
static __device__ __forceinline__ float sigm(float x) {
    float e;
    asm("ex2.approx.f32 %0, %1;" : "=f"(e) : "f"(-1.4426950408889634f * x));
    float r;
    asm("rcp.approx.f32 %0, %1;" : "=f"(r) : "f"(1.0f + e));
    return r;
}
static __device__ __forceinline__ void ldsm4(uint32_t* r, uint32_t addr) {
    asm volatile("ldmatrix.sync.aligned.m8n8.x4.shared.b16 {%0,%1,%2,%3}, [%4];"
                 : "=r"(r[0]), "=r"(r[1]), "=r"(r[2]), "=r"(r[3]) : "r"(addr));
}
static __device__ __forceinline__ void ldsm2(uint32_t* r, uint32_t addr) {
    asm volatile("ldmatrix.sync.aligned.m8n8.x2.shared.b16 {%0,%1}, [%2];"
                 : "=r"(r[0]), "=r"(r[1]) : "r"(addr));
}
static __device__ __forceinline__ void mma16816(float* d, const uint32_t* a,
                                                const uint32_t* b) {
    asm volatile(
        "mma.sync.aligned.m16n8k16.row.col.f32.bf16.bf16.f32 "
        "{%0,%1,%2,%3}, {%4,%5,%6,%7}, {%8,%9}, {%0,%1,%2,%3};"
        : "+f"(d[0]), "+f"(d[1]), "+f"(d[2]), "+f"(d[3])
        : "r"(a[0]), "r"(a[1]), "r"(a[2]), "r"(a[3]), "r"(b[0]), "r"(b[1]));
}

__global__ void __launch_bounds__(256, 1) lstm_mma_kernel(
    const float* __restrict__ x,  const float* __restrict__ W,
    const float* __restrict__ U,  const float* __restrict__ b,
    const float* __restrict__ W1, const float* __restrict__ b1,
    const float* __restrict__ W2, const float* __restrict__ b2,
    float* __restrict__ out)
{
    // weights (init-only; reused as fp32 h buffer for the heads at the end)
    __shared__ __align__(16) __nv_bfloat16 wsm[128 * KS];   // [gate][K] 26.6KB
    __shared__ __align__(16) __nv_bfloat16 bx[ROWS * KS];   // [row][K]  13.3KB

    const int tid = threadIdx.x;
    const int l   = tid & 31;
    const int w   = tid >> 5;
    const int gid = l >> 2, tig = l & 3;
    const int mg  = w & 1;        // unit half (16 units)
    const int ng  = w >> 1;       // row quarter (16 rows)

    // ---- fill weight smem: K layout [Uhi 0..31 | Ulo 32..63 | Whi 64..79 | Wlo 80..95]
    for (int idx = tid; idx < 128 * 96; idx += 256) {
        int g = idx / 96, k = idx - g * 96;
        float v;
        if (k < 32)      v = bhi(U[k * 128 + g]);
        else if (k < 64) { float u = U[(k - 32) * 128 + g]; v = u - bhi(u); }
        else if (k < 80) v = bhi(W[(k - 64) * 128 + g]);
        else             { float t = W[(k - 80) * 128 + g]; v = t - bhi(t); }
        wsm[g * KS + k] = __float2bfloat16_rn(v);
    }
    // zero activation tile (h0 = 0; x region overwritten below)
    for (int idx = tid; idx < ROWS * KS; idx += 256)
        bx[idx] = __float2bfloat16_rn(0.0f);
    __syncthreads();

    // ---- A fragments (weights) into registers: afr[mt][ks][4]
    const uint32_t wsmu = s2u(wsm);
    uint32_t afr[4][6][4];
    {
        int laneRow = (l & 7) + 8 * ((l >> 3) & 1);
        int laneK   = 8 * (l >> 4);
#pragma unroll
        for (int mt = 0; mt < 4; ++mt) {
            int Gmt = 32 * mt + 16 * mg;
#pragma unroll
            for (int ks = 0; ks < 6; ++ks) {
                uint32_t addr = wsmu + ((Gmt + laneRow) * KS + 16 * ks + laneK) * 2;
                ldsm4(afr[mt][ks], addr);
            }
        }
    }
    // biases for this thread's gates
    float bv[4][2];
#pragma unroll
    for (int mt = 0; mt < 4; ++mt) {
        bv[mt][0] = b[32 * mt + 16 * mg + gid];
        bv[mt][1] = b[32 * mt + 16 * mg + gid + 8];
    }

    // ---- stage x(0), prefetch x(1). thread t -> row t>>2, quarter t&3
    const int xrow = tid >> 2, xq = tid & 3;
    const float* xp = x + ((size_t)blockIdx.x * ROWS + xrow) * (TT * 16) + xq * 4;
    {
        float4 v = *(const float4*)xp;
        *(uint2*)((char*)bx + xrow * (KS * 2) + (64 + 4 * xq) * 2) =
            make_uint2(bpack(v.x, v.y), bpack(v.z, v.w));
        *(uint2*)((char*)bx + xrow * (KS * 2) + (80 + 4 * xq) * 2) =
            make_uint2(bpack(v.x - bhi(v.x), v.y - bhi(v.y)),
                       bpack(v.z - bhi(v.z), v.w - bhi(v.w)));
    }
    float4 pf = *(const float4*)(xp + 16);   // x(1)
    __syncthreads();

    const uint32_t bxu = s2u(bx);
    // ldmatrix B lane base (lanes 0..15 meaningful for x2)
    const uint32_t bb0 = bxu + ((16 * ng + (l & 7)) * KS + 8 * ((l >> 3) & 1)) * 2;

    float cst[2][2][2];   // [unit-half h][nt][p]
    float hrg[2][2][2];
#pragma unroll
    for (int i = 0; i < 2; ++i)
#pragma unroll
        for (int j = 0; j < 2; ++j)
#pragma unroll
            for (int k = 0; k < 2; ++k) { cst[i][j][k] = 0.0f; hrg[i][j][k] = 0.0f; }

#pragma unroll 1
    for (int t = 0; t < TT; ++t) {
        // ---- phase 1: load all B fragments (reads h(t), x(t))
        uint32_t bfr[6][2][2];
#pragma unroll
        for (int nt = 0; nt < 2; ++nt)
#pragma unroll
            for (int ks = 0; ks < 6; ++ks)
                ldsm2(bfr[ks][nt], bb0 + nt * (8 * KS * 2) + ks * 32);
        __syncthreads();

        // ---- phase 2a: stage x(t+1), prefetch x(t+2)
        *(uint2*)((char*)bx + xrow * (KS * 2) + (64 + 4 * xq) * 2) =
            make_uint2(bpack(pf.x, pf.y), bpack(pf.z, pf.w));
        *(uint2*)((char*)bx + xrow * (KS * 2) + (80 + 4 * xq) * 2) =
            make_uint2(bpack(pf.x - bhi(pf.x), pf.y - bhi(pf.y)),
                       bpack(pf.z - bhi(pf.z), pf.w - bhi(pf.w)));
        {
            int tn = (t + 2 < TT) ? t + 2 : TT - 1;
            pf = *(const float4*)(xp + tn * 16);
        }

        // ---- phase 2b: MMA chains (9 products per (mt,nt))
        float dac[4][2][4];
#pragma unroll
        for (int mt = 0; mt < 4; ++mt)
#pragma unroll
            for (int nt = 0; nt < 2; ++nt) {
                dac[mt][nt][0] = bv[mt][0]; dac[mt][nt][1] = bv[mt][0];
                dac[mt][nt][2] = bv[mt][1]; dac[mt][nt][3] = bv[mt][1];
            }
#pragma unroll
        for (int mt = 0; mt < 4; ++mt)
#pragma unroll
            for (int nt = 0; nt < 2; ++nt) {
                float* d = dac[mt][nt];
                mma16816(d, afr[mt][0], bfr[0][nt]);   // Uhi . h_hi
                mma16816(d, afr[mt][1], bfr[1][nt]);
                mma16816(d, afr[mt][0], bfr[2][nt]);   // Uhi . h_lo
                mma16816(d, afr[mt][1], bfr[3][nt]);
                mma16816(d, afr[mt][2], bfr[0][nt]);   // Ulo . h_hi
                mma16816(d, afr[mt][3], bfr[1][nt]);
                mma16816(d, afr[mt][4], bfr[4][nt]);   // Whi . x_hi
                mma16816(d, afr[mt][4], bfr[5][nt]);   // Whi . x_lo
                mma16816(d, afr[mt][5], bfr[4][nt]);   // Wlo . x_hi
            }

        // ---- phase 2c: state update (fully thread-local) + h writeback
#pragma unroll
        for (int h = 0; h < 2; ++h) {
            const int u = 16 * mg + gid + 8 * h;
#pragma unroll
            for (int nt = 0; nt < 2; ++nt)
#pragma unroll
                for (int p = 0; p < 2; ++p) {
                    const int e = 2 * h + p;
                    float si = sigm(dac[0][nt][e]);
                    float sf = sigm(dac[1][nt][e]);
                    float cc = fmaxf(dac[2][nt][e], 0.0f);
                    float so = sigm(dac[3][nt][e]);
                    float c  = sf * cst[h][nt][p] + si * cc;
                    cst[h][nt][p] = c;
                    float hv = so * fmaxf(c, 0.0f);
                    hrg[h][nt][p] = hv;
                    int r = 16 * ng + 8 * nt + 2 * tig + p;
                    float hh = bhi(hv);
                    bx[r * KS + u]      = __float2bfloat16_rn(hv);
                    bx[r * KS + 32 + u] = __float2bfloat16_rn(hv - hh);
                }
        }
        __syncthreads();
    }

    // ---- output heads: reuse wsm as fp32 h buffer [64 rows][32 units]
    float* hsm = (float*)wsm;
#pragma unroll
    for (int h = 0; h < 2; ++h) {
        const int u = 16 * mg + gid + 8 * h;
#pragma unroll
        for (int nt = 0; nt < 2; ++nt)
#pragma unroll
            for (int p = 0; p < 2; ++p) {
                int r = 16 * ng + 8 * nt + 2 * tig + p;
                hsm[r * 32 + u] = hrg[h][nt][p];
            }
    }
    __syncthreads();

    for (int idx = tid; idx < ROWS * DD; idx += 256) {
        int r = idx / DD, d = idx - r * DD;
        const float* hr = hsm + r * 32;
        float aL = b1[d], aA = b2[d];
#pragma unroll
        for (int u = 0; u < 32; ++u) {
            float hu = hr[u];
            aL = fmaf(hu, W1[u * DD + d], aL);
            aA = fmaf(hu, W2[u * DD + d], aA);
        }
        size_t grow = (size_t)blockIdx.x * ROWS + r;
        out[grow * DD + d] = aL;
        out[(8192 + grow) * DD + d] = aA;
    }
}

extern "C" void kernel_launch(void* const* d_in, const int* in_sizes, int n_in,
                              void* d_out, int out_size) {
    const float* x  = (const float*)d_in[0];
    const float* W  = (const float*)d_in[1];
    const float* U  = (const float*)d_in[2];
    const float* b  = (const float*)d_in[3];
    const float* W1 = (const float*)d_in[4];
    const float* b1 = (const float*)d_in[5];
    const float* W2 = (const float*)d_in[6];
    const float* b2 = (const float*)d_in[7];
    float* out = (float*)d_out;

    // 8192 rows / 64 per CTA = 128 CTAs, 256 threads
    lstm_mma_kernel<<<128, 256>>>(x, W, U, b, W1, b1, W2, b2, out);
}

// round 6
// speedup vs baseline: 2.0020x; 1.0435x over previous
#include <cuda_runtime.h>
#include <cuda_bf16.h>
#include <cstdint>

// lstm_model_8873402433789 R6 — mma.sync bf16 LSTM, pair-decoupled.
// 128 CTAs x 64 rows. 4 independent warp-pairs per CTA (16 rows each) sync via
// named barriers only -> cross-pair tensor/MUFU overlap per SMSP.
// Batched-rcp sigmoid (4 MUFU per i/f/o triple), ldsm x4 B loads.

#define TT 200
#define ROWS 64
#define KS 104          // padded K stride (bf16): 96 data + 8 pad (conflict-free ldsm)
#define DD 60

static __device__ __forceinline__ uint32_t s2u(const void* p) {
    uint32_t a;
    asm("{ .reg .u64 t; cvta.to.shared.u64 t, %1; cvt.u32.u64 %0, t; }"
        : "=r"(a) : "l"(p));
    return a;
}
static __device__ __forceinline__ float bhi(float a) {
    return __bfloat162float(__float2bfloat16_rn(a));
}
static __device__ __forceinline__ uint32_t bpack(float a, float b) {
    __nv_bfloat162 t = __float22bfloat162_rn(make_float2(a, b));
    return *(uint32_t*)&t;
}
static __device__ __forceinline__ float ex2n(float g) {   // exp(-g)
    float e;
    asm("ex2.approx.f32 %0, %1;" : "=f"(e) : "f"(-1.4426950408889634f * g));
    return e;
}
static __device__ __forceinline__ float frcp(float a) {
    float r;
    asm("rcp.approx.f32 %0, %1;" : "=f"(r) : "f"(a));
    return r;
}
static __device__ __forceinline__ void ldsm4(uint32_t* r, uint32_t addr) {
    asm volatile("ldmatrix.sync.aligned.m8n8.x4.shared.b16 {%0,%1,%2,%3}, [%4];"
                 : "=r"(r[0]), "=r"(r[1]), "=r"(r[2]), "=r"(r[3]) : "r"(addr));
}
static __device__ __forceinline__ void mma16816(float* d, const uint32_t* a,
                                                const uint32_t* b) {
    asm volatile(
        "mma.sync.aligned.m16n8k16.row.col.f32.bf16.bf16.f32 "
        "{%0,%1,%2,%3}, {%4,%5,%6,%7}, {%8,%9}, {%0,%1,%2,%3};"
        : "+f"(d[0]), "+f"(d[1]), "+f"(d[2]), "+f"(d[3])
        : "r"(a[0]), "r"(a[1]), "r"(a[2]), "r"(a[3]), "r"(b[0]), "r"(b[1]));
}

__global__ void __launch_bounds__(256, 1) lstm_mma2_kernel(
    const float* __restrict__ x,  const float* __restrict__ W,
    const float* __restrict__ U,  const float* __restrict__ b,
    const float* __restrict__ W1, const float* __restrict__ b1,
    const float* __restrict__ W2, const float* __restrict__ b2,
    float* __restrict__ out)
{
    __shared__ __align__(16) __nv_bfloat16 wsm[128 * KS];   // [gate][K]
    __shared__ __align__(16) __nv_bfloat16 bx[ROWS * KS];   // [row][K]

    const int tid = threadIdx.x;
    const int l   = tid & 31;
    const int w   = tid >> 5;
    const int gid = l >> 2, tig = l & 3;
    const int mg  = w & 1;        // unit half (16 units)
    const int ng  = w >> 1;       // row quarter (16 rows) == pair id
    const int pl  = mg * 32 + l;  // pair-local thread id (0..63)

    // ---- weight smem: K layout [Uhi 0..31 | Ulo 32..63 | Whi 64..79 | Wlo 80..95]
    for (int idx = tid; idx < 128 * 96; idx += 256) {
        int g = idx / 96, k = idx - g * 96;
        float v;
        if (k < 32)      v = bhi(U[k * 128 + g]);
        else if (k < 64) { float u = U[(k - 32) * 128 + g]; v = u - bhi(u); }
        else if (k < 80) v = bhi(W[(k - 64) * 128 + g]);
        else             { float t = W[(k - 80) * 128 + g]; v = t - bhi(t); }
        wsm[g * KS + k] = __float2bfloat16_rn(v);
    }
    for (int idx = tid; idx < ROWS * KS; idx += 256)
        bx[idx] = __float2bfloat16_rn(0.0f);
    __syncthreads();

    // ---- A fragments (weights): afr[mt][ks][4]
    const uint32_t wsmu = s2u(wsm);
    uint32_t afr[4][6][4];
    {
        int laneRow = (l & 7) + 8 * ((l >> 3) & 1);
        int laneK   = 8 * (l >> 4);
#pragma unroll
        for (int mt = 0; mt < 4; ++mt) {
            int Gmt = 32 * mt + 16 * mg;
#pragma unroll
            for (int ks = 0; ks < 6; ++ks)
                ldsm4(afr[mt][ks], wsmu + ((Gmt + laneRow) * KS + 16 * ks + laneK) * 2);
        }
    }
    float bv[4][2];
#pragma unroll
    for (int mt = 0; mt < 4; ++mt) {
        bv[mt][0] = b[32 * mt + 16 * mg + gid];
        bv[mt][1] = b[32 * mt + 16 * mg + gid + 8];
    }

    // ---- pair-local x staging map: 64 threads stage 16 rows x 4 quarters
    const int prow = 16 * ng + (pl >> 2);   // row this thread stages
    const int pxq  = pl & 3;
    const float* xp = x + ((size_t)blockIdx.x * ROWS + prow) * (TT * 16) + pxq * 4;
    {
        float4 v = *(const float4*)xp;      // x(0)
        *(uint2*)((char*)bx + prow * (KS * 2) + (64 + 4 * pxq) * 2) =
            make_uint2(bpack(v.x, v.y), bpack(v.z, v.w));
        *(uint2*)((char*)bx + prow * (KS * 2) + (80 + 4 * pxq) * 2) =
            make_uint2(bpack(v.x - bhi(v.x), v.y - bhi(v.y)),
                       bpack(v.z - bhi(v.z), v.w - bhi(v.w)));
    }
    float4 pf = *(const float4*)(xp + 16);  // x(1)
    __syncthreads();

    const uint32_t bxu = s2u(bx);
    // ldsm x4 B base: n-row = 16ng+(l&7); k-offset = 16*(l>>4) + 8*((l>>3)&1)
    const uint32_t bb0 = bxu +
        ((16 * ng + (l & 7)) * KS + 16 * (l >> 4) + 8 * ((l >> 3) & 1)) * 2;
    const int bar = 1 + ng;     // named barrier per pair

    float cst[2][2][2], hrg[2][2][2];
#pragma unroll
    for (int i = 0; i < 2; ++i)
#pragma unroll
        for (int j = 0; j < 2; ++j)
#pragma unroll
            for (int k = 0; k < 2; ++k) { cst[i][j][k] = 0.0f; hrg[i][j][k] = 0.0f; }

#pragma unroll 1
    for (int t = 0; t < TT; ++t) {
        // ---- load B fragments (h(t), x(t)) : 3 ldsm4 per nt
        uint32_t bfr[6][2][2];
#pragma unroll
        for (int nt = 0; nt < 2; ++nt)
#pragma unroll
            for (int kp = 0; kp < 3; ++kp) {
                uint32_t tmp[4];
                ldsm4(tmp, bb0 + nt * (8 * KS * 2) + kp * 64);
                bfr[2 * kp][nt][0]     = tmp[0]; bfr[2 * kp][nt][1]     = tmp[1];
                bfr[2 * kp + 1][nt][0] = tmp[2]; bfr[2 * kp + 1][nt][1] = tmp[3];
            }
        asm volatile("bar.sync %0, %1;" :: "r"(bar), "r"(64) : "memory");

        // ---- stage x(t+1), prefetch x(t+2) (overlaps MMA)
        *(uint2*)((char*)bx + prow * (KS * 2) + (64 + 4 * pxq) * 2) =
            make_uint2(bpack(pf.x, pf.y), bpack(pf.z, pf.w));
        *(uint2*)((char*)bx + prow * (KS * 2) + (80 + 4 * pxq) * 2) =
            make_uint2(bpack(pf.x - bhi(pf.x), pf.y - bhi(pf.y)),
                       bpack(pf.z - bhi(pf.z), pf.w - bhi(pf.w)));
        {
            int tn = (t + 2 < TT) ? t + 2 : TT - 1;
            pf = *(const float4*)(xp + tn * 16);
        }

        // ---- MMA chains (9 products per (mt,nt))
        float dac[4][2][4];
#pragma unroll
        for (int mt = 0; mt < 4; ++mt)
#pragma unroll
            for (int nt = 0; nt < 2; ++nt) {
                dac[mt][nt][0] = bv[mt][0]; dac[mt][nt][1] = bv[mt][0];
                dac[mt][nt][2] = bv[mt][1]; dac[mt][nt][3] = bv[mt][1];
            }
#pragma unroll
        for (int mt = 0; mt < 4; ++mt)
#pragma unroll
            for (int nt = 0; nt < 2; ++nt) {
                float* d = dac[mt][nt];
                mma16816(d, afr[mt][0], bfr[0][nt]);   // Uhi . h_hi
                mma16816(d, afr[mt][1], bfr[1][nt]);
                mma16816(d, afr[mt][0], bfr[2][nt]);   // Uhi . h_lo
                mma16816(d, afr[mt][1], bfr[3][nt]);
                mma16816(d, afr[mt][2], bfr[0][nt]);   // Ulo . h_hi
                mma16816(d, afr[mt][3], bfr[1][nt]);
                mma16816(d, afr[mt][4], bfr[4][nt]);   // Whi . x_hi
                mma16816(d, afr[mt][4], bfr[5][nt]);   // Whi . x_lo
                mma16816(d, afr[mt][5], bfr[4][nt]);   // Wlo . x_hi
            }

        // ---- state update: batched-rcp sigmoid (3 ex2 + 1 rcp per element)
#pragma unroll
        for (int h = 0; h < 2; ++h) {
            const int u = 16 * mg + gid + 8 * h;
#pragma unroll
            for (int nt = 0; nt < 2; ++nt)
#pragma unroll
                for (int p = 0; p < 2; ++p) {
                    const int e = 2 * h + p;
                    float a  = 1.0f + ex2n(dac[0][nt][e]);   // 1+exp(-gi)
                    float bq = 1.0f + ex2n(dac[1][nt][e]);   // 1+exp(-gf)
                    float cq = 1.0f + ex2n(dac[3][nt][e]);   // 1+exp(-go)
                    float ab = a * bq, bc = bq * cq, ac = a * cq;
                    float r  = frcp(ab * cq);
                    float si = bc * r, sf = ac * r, so = ab * r;
                    float cc = fmaxf(dac[2][nt][e], 0.0f);
                    float c  = sf * cst[h][nt][p] + si * cc;
                    cst[h][nt][p] = c;
                    float hv = so * fmaxf(c, 0.0f);
                    hrg[h][nt][p] = hv;
                    int rr = 16 * ng + 8 * nt + 2 * tig + p;
                    float hh = bhi(hv);
                    bx[rr * KS + u]      = __float2bfloat16_rn(hv);
                    bx[rr * KS + 32 + u] = __float2bfloat16_rn(hv - hh);
                }
        }
        asm volatile("bar.sync %0, %1;" :: "r"(bar), "r"(64) : "memory");
    }

    // ---- output heads: reuse wsm as fp32 h buffer [64 rows][32 units]
    __syncthreads();
    float* hsm = (float*)wsm;
#pragma unroll
    for (int h = 0; h < 2; ++h) {
        const int u = 16 * mg + gid + 8 * h;
#pragma unroll
        for (int nt = 0; nt < 2; ++nt)
#pragma unroll
            for (int p = 0; p < 2; ++p) {
                int rr = 16 * ng + 8 * nt + 2 * tig + p;
                hsm[rr * 32 + u] = hrg[h][nt][p];
            }
    }
    __syncthreads();

    for (int idx = tid; idx < ROWS * DD; idx += 256) {
        int rr = idx / DD, d = idx - rr * DD;
        const float* hr = hsm + rr * 32;
        float aL = b1[d], aA = b2[d];
#pragma unroll
        for (int u = 0; u < 32; ++u) {
            float hu = hr[u];
            aL = fmaf(hu, W1[u * DD + d], aL);
            aA = fmaf(hu, W2[u * DD + d], aA);
        }
        size_t grow = (size_t)blockIdx.x * ROWS + rr;
        out[grow * DD + d] = aL;
        out[(8192 + grow) * DD + d] = aA;
    }
}

extern "C" void kernel_launch(void* const* d_in, const int* in_sizes, int n_in,
                              void* d_out, int out_size) {
    const float* x  = (const float*)d_in[0];
    const float* W  = (const float*)d_in[1];
    const float* U  = (const float*)d_in[2];
    const float* b  = (const float*)d_in[3];
    const float* W1 = (const float*)d_in[4];
    const float* b1 = (const float*)d_in[5];
    const float* W2 = (const float*)d_in[6];
    const float* b2 = (const float*)d_in[7];
    float* out = (float*)d_out;

    lstm_mma2_kernel<<<128, 256>>>(x, W, U, b, W1, b1, W2, b2, out);
}